// round 9
// baseline (speedup 1.0000x reference)
#include <cuda_runtime.h>
#include <cuda_fp16.h>
#include <cstdint>

// Problem constants
#define Bb 4
#define Cc 64
#define Dd 8
#define Nn 4096          // H*W
#define LOG2E 1.4426950408889634f
#define TK 128           // keys per tile
#define NQ 128           // queries per CTA
#define KS 2             // key splits
#define NTS (Nn / TK / KS)   // 16 tiles per CTA

// Scratch (allocation-free rule: __device__ globals)
__device__ float  g_q[Bb * Nn * Dd];                 // [b][n][d] f32, scaled by log2e
__device__ __half g_kh[Bb * Nn * Dd];                // [b][n][d] f16
__device__ __half g_vh[Bb * Nn * Cc];                // [b][n][c] f16 key-major
__device__ float  g_po[Bb * KS * Cc * Nn];           // partial O (unnormalized)
__device__ float  g_pl[Bb * KS * Nn];                // partial l
__device__ int    g_ctr[Bb * (Nn / NQ)];             // split-K fixup counters (zero-init)

// ---------------- PTX helpers (baseline ISA only) ----------------
__device__ __forceinline__ uint32_t smem_u32(const void* p) {
    uint32_t a;
    asm("{ .reg .u64 t; cvta.to.shared.u64 t, %1; cvt.u32.u64 %0, t; }" : "=r"(a) : "l"(p));
    return a;
}
__device__ __forceinline__ unsigned long long pack2(float a, float b) {
    unsigned long long r;
    asm("mov.b64 %0, {%1, %2};" : "=l"(r) : "f"(a), "f"(b));
    return r;
}
__device__ __forceinline__ void unpack2(unsigned long long v, float& a, float& b) {
    asm("mov.b64 {%0, %1}, %2;" : "=f"(a), "=f"(b) : "l"(v));
}
__device__ __forceinline__ unsigned long long ffma2(unsigned long long a,
                                                    unsigned long long b,
                                                    unsigned long long c) {
    unsigned long long d;
    asm("fma.rn.f32x2 %0, %1, %2, %3;" : "=l"(d) : "l"(a), "l"(b), "l"(c));
    return d;
}
// d = {lo, hi} f16x2 (lo in low half)
__device__ __forceinline__ uint32_t cvtf16x2(float lo, float hi) {
    uint32_t r;
    asm("cvt.rn.f16x2.f32 %0, %1, %2;" : "=r"(r) : "f"(hi), "f"(lo));
    return r;
}
__device__ __forceinline__ uint32_t ex2h2(uint32_t a) {
    uint32_t r;
    asm("ex2.approx.f16x2 %0, %1;" : "=r"(r) : "r"(a));
    return r;
}
__device__ __forceinline__ void lds_v2u64(uint32_t a, unsigned long long& x,
                                          unsigned long long& y) {
    asm volatile("ld.shared.v2.u64 {%0, %1}, [%2];" : "=l"(x), "=l"(y) : "r"(a));
}
__device__ __forceinline__ void ldsm2(uint32_t& r0, uint32_t& r1, uint32_t a) {
    asm volatile("ldmatrix.sync.aligned.m8n8.x2.shared.b16 {%0, %1}, [%2];"
                 : "=r"(r0), "=r"(r1) : "r"(a));
}
__device__ __forceinline__ void ldsm4t(uint32_t& r0, uint32_t& r1, uint32_t& r2,
                                       uint32_t& r3, uint32_t a) {
    asm volatile("ldmatrix.sync.aligned.m8n8.x4.trans.shared.b16 {%0, %1, %2, %3}, [%4];"
                 : "=r"(r0), "=r"(r1), "=r"(r2), "=r"(r3) : "r"(a));
}
__device__ __forceinline__ void cp16(uint32_t dst, const void* src) {
    asm volatile("cp.async.ca.shared.global [%0], [%1], 16;" :: "r"(dst), "l"(src) : "memory");
}
#define CP_COMMIT() asm volatile("cp.async.commit_group;" ::: "memory")
#define CP_WAIT1()  asm volatile("cp.async.wait_group 1;" ::: "memory")
#define CP_WAIT0()  asm volatile("cp.async.wait_group 0;" ::: "memory")

// S[16q x 8k] = Q[16x8] * K^T, f32 accum from zero
__device__ __forceinline__ void mma_qk8(float s[4], uint32_t a0, uint32_t a1,
                                        uint32_t b0) {
    asm volatile(
        "mma.sync.aligned.m16n8k8.row.col.f32.f16.f16.f32 "
        "{%0,%1,%2,%3}, {%4,%5}, {%6}, {%7,%7,%7,%7};"
        : "=f"(s[0]), "=f"(s[1]), "=f"(s[2]), "=f"(s[3])
        : "r"(a0), "r"(a1), "r"(b0), "f"(0.0f));
}
__device__ __forceinline__ void mma16816(float d[4], uint32_t a0, uint32_t a1,
                                         uint32_t a2, uint32_t a3,
                                         uint32_t b0, uint32_t b1) {
    asm volatile(
        "mma.sync.aligned.m16n8k16.row.col.f32.f16.f16.f32 "
        "{%0,%1,%2,%3}, {%4,%5,%6,%7}, {%8,%9}, {%0,%1,%2,%3};"
        : "+f"(d[0]), "+f"(d[1]), "+f"(d[2]), "+f"(d[3])
        : "r"(a0), "r"(a1), "r"(a2), "r"(a3), "r"(b0), "r"(b1));
}

// ============================================================
// Kernel 1: fused 1x1-conv QKV projection — weights in registers,
//   x tile through shared (broadcast LDS). 128-pixel tiles,
//   640 threads = 8 pixel-groups x 80 output channels -> grid 128
//   (single CTA wave on 148 SMs).
//   o in [0,64): V; [64,72): Q (scaled by log2e); [72,80): K.
// grid (Nn/128, Bb)
// ============================================================
__global__ void __launch_bounds__(640) qkv_kernel(
    const float* __restrict__ x,
    const float* __restrict__ Wq, const float* __restrict__ bq,
    const float* __restrict__ Wk, const float* __restrict__ bk,
    const float* __restrict__ Wv, const float* __restrict__ bv)
{
    __shared__ __align__(16) float sx[Cc * 128];   // [c][px] 32 KB
    const uint32_t sb = smem_u32(sx);

    const int tid = threadIdx.x;
    const int pg  = tid / 80;        // 0..7 (16 pixels each)
    const int o   = tid - pg * 80;   // 0..79
    const int b   = blockIdx.y;
    const int n0  = blockIdx.x * 128;

    // ---- stage x tile [64c][128px] via cp.async (2048 x 16B) ----
#pragma unroll
    for (int i = 0; i < 4; i++) {
        const int id = tid + i * 640;
        if (id < 2048) {
            const int c = id >> 5, chunk = id & 31;
            cp16(sb + (uint32_t)(c * 512 + chunk * 16),
                 &x[(size_t)(b * Cc + c) * Nn + n0 + chunk * 4]);
        }
    }
    CP_COMMIT();

    // ---- select weight row + bias ----
    const float* wsrc;
    float bias, scale;
    if (o < 64)      { wsrc = Wv + o * 64;        bias = bv[o];              scale = 1.0f; }
    else if (o < 72) { wsrc = Wq + (o - 64) * 64; bias = bq[o - 64] * LOG2E; scale = LOG2E; }
    else             { wsrc = Wk + (o - 72) * 64; bias = bk[o - 72];         scale = 1.0f; }
    const float4* wp4 = (const float4*)wsrc;

    float4 nw0 = wp4[0], nw1 = wp4[1], nw2 = wp4[2], nw3 = wp4[3];

    unsigned long long acc[8];
#pragma unroll
    for (int i = 0; i < 8; i++) acc[i] = pack2(0.0f, 0.0f);

    CP_WAIT0();
    __syncthreads();

    const uint32_t xrow = sb + (uint32_t)(pg * 64);
#pragma unroll
    for (int cb = 0; cb < 4; cb++) {
        float wf[16];
        wf[0] = nw0.x * scale; wf[1] = nw0.y * scale; wf[2] = nw0.z * scale; wf[3] = nw0.w * scale;
        wf[4] = nw1.x * scale; wf[5] = nw1.y * scale; wf[6] = nw1.z * scale; wf[7] = nw1.w * scale;
        wf[8] = nw2.x * scale; wf[9] = nw2.y * scale; wf[10] = nw2.z * scale; wf[11] = nw2.w * scale;
        wf[12] = nw3.x * scale; wf[13] = nw3.y * scale; wf[14] = nw3.z * scale; wf[15] = nw3.w * scale;
        if (cb < 3) {
            nw0 = wp4[(cb + 1) * 4 + 0];
            nw1 = wp4[(cb + 1) * 4 + 1];
            nw2 = wp4[(cb + 1) * 4 + 2];
            nw3 = wp4[(cb + 1) * 4 + 3];
        }

#pragma unroll
        for (int cc = 0; cc < 16; cc++) {
            const uint32_t xa = xrow + (uint32_t)((cb * 16 + cc) * 512);
            unsigned long long x0, x1, x2, x3, x4, x5, x6, x7;
            lds_v2u64(xa,      x0, x1);
            lds_v2u64(xa + 16, x2, x3);
            lds_v2u64(xa + 32, x4, x5);
            lds_v2u64(xa + 48, x6, x7);
            const unsigned long long wp = pack2(wf[cc], wf[cc]);
            acc[0] = ffma2(wp, x0, acc[0]);
            acc[1] = ffma2(wp, x1, acc[1]);
            acc[2] = ffma2(wp, x2, acc[2]);
            acc[3] = ffma2(wp, x3, acc[3]);
            acc[4] = ffma2(wp, x4, acc[4]);
            acc[5] = ffma2(wp, x5, acc[5]);
            acc[6] = ffma2(wp, x6, acc[6]);
            acc[7] = ffma2(wp, x7, acc[7]);
        }
    }

    // ---- epilogue: add bias, store per class ----
    if (o < 64) {
        __half* vd = &g_vh[((size_t)b * Nn + n0 + pg * 16) * Cc + o];
#pragma unroll
        for (int pp = 0; pp < 8; pp++) {
            float lo, hi;
            unpack2(acc[pp], lo, hi);
            vd[(2 * pp) * Cc]     = __float2half_rn(lo + bias);
            vd[(2 * pp + 1) * Cc] = __float2half_rn(hi + bias);
        }
    } else if (o < 72) {
        const int d = o - 64;
        float* qd = &g_q[((size_t)b * Nn + n0 + pg * 16) * Dd + d];
#pragma unroll
        for (int pp = 0; pp < 8; pp++) {
            float lo, hi;
            unpack2(acc[pp], lo, hi);
            qd[(2 * pp) * Dd]     = lo + bias;
            qd[(2 * pp + 1) * Dd] = hi + bias;
        }
    } else {
        const int d = o - 72;
        __half* kd = &g_kh[((size_t)b * Nn + n0 + pg * 16) * Dd + d];
#pragma unroll
        for (int pp = 0; pp < 8; pp++) {
            float lo, hi;
            unpack2(acc[pp], lo, hi);
            kd[(2 * pp) * Dd]     = __float2half_rn(lo + bias);
            kd[(2 * pp + 1) * Dd] = __float2half_rn(hi + bias);
        }
    }
}

// ============================================================
// Kernel 2: attention + in-kernel split-K fixup.
//   grid (32, KS, Bb), 256 threads = 8 warps (16 queries each).
//   Each split writes po/pl; the last-arriving CTA per (b,rowblk)
//   merges both splits and writes out = gamma*(O/l) + x.
// ============================================================
__global__ void __launch_bounds__(256) attn_kernel(
    const float* __restrict__ x,
    const float* __restrict__ gamma,
    float* __restrict__ out)
{
    // 2 bufs x (2KB K + 16KB V); epilogue reuses as 64x132 f32 (33.8KB)
    __shared__ __align__(16) char smem[36864];
    __shared__ int s_last;
    const uint32_t sb = smem_u32(smem);

    const int tid  = threadIdx.x;
    const int w    = tid >> 5;
    const int lane = tid & 31;
    const int gid  = lane >> 2;   // 0..7
    const int tg   = lane & 3;    // 0..3
    const int b    = blockIdx.z;
    const int s    = blockIdx.y;
    const int row0 = blockIdx.x * NQ;
    const int key0 = s * (Nn / KS);

    // ---- Q A-frags for QK mma (constant) ----
    uint32_t qA0, qA1;
    {
        const float* qr = &g_q[((size_t)b * Nn + row0 + w * 16 + gid) * Dd + 2 * tg];
        const float2 qa = *(const float2*)qr;
        const float2 qc = *(const float2*)(qr + 8 * Dd);
        qA0 = cvtf16x2(qa.x, qa.y);
        qA1 = cvtf16x2(qc.x, qc.y);
    }

    // ---- loop-constant ldmatrix lane offsets ----
    const int koffV = ((lane >> 3) & 1) * 8 + (lane & 7);   // key offset within 16
    const int jhalf = lane >> 4;                            // chunk half (0/1)
    uint32_t vmoff[4];
#pragma unroll
    for (int g = 0; g < 4; g++)
        vmoff[g] = (uint32_t)(koffV * 128 + (((g * 2 + jhalf) ^ (koffV & 7)) * 16));
    const uint32_t kmoff = (uint32_t)((lane & 15) * 16);

    float dac[8][4];
#pragma unroll
    for (int nt = 0; nt < 8; nt++)
#pragma unroll
        for (int i = 0; i < 4; i++) dac[nt][i] = 0.f;
    float dl[4] = {0.f, 0.f, 0.f, 0.f};
    const uint32_t ONES = 0x3C003C00u;

    auto prefetch = [&](int t, int buf) {
        const uint32_t kdst = sb + (uint32_t)buf * 18432u;
        const uint32_t vdst = kdst + 2048u;
        if (tid < 128)
            cp16(kdst + (uint32_t)(tid * 16),
                 &g_kh[((size_t)b * Nn + key0 + t * TK + tid) * Dd]);
#pragma unroll
        for (int j = 0; j < 4; j++) {
            const int id = tid + 256 * j;
            const int key = id >> 3, ch = id & 7;
            cp16(vdst + (uint32_t)(key * 128 + ((ch ^ (key & 7)) * 16)),
                 &g_vh[((size_t)(b * Nn + key0 + t * TK + key)) * Cc + ch * 8]);
        }
    };

    prefetch(0, 0);
    CP_COMMIT();

#pragma unroll 1
    for (int t = 0; t < NTS; t++) {
        if (t + 1 < NTS) { prefetch(t + 1, (t + 1) & 1); CP_COMMIT(); CP_WAIT1(); }
        else             { CP_WAIT0(); }
        __syncthreads();

        const uint32_t Kb = sb + (uint32_t)(t & 1) * 18432u;
        const uint32_t Vb = Kb + 2048u;

#pragma unroll
        for (int ks = 0; ks < 8; ks++) {
            uint32_t kb0, kb1;
            ldsm2(kb0, kb1, Kb + (uint32_t)(ks * 256) + kmoff);
            float s0[4], s1[4];
            mma_qk8(s0, qA0, qA1, kb0);
            mma_qk8(s1, qA0, qA1, kb1);

            const uint32_t a0 = ex2h2(cvtf16x2(s0[0], s0[1]));
            const uint32_t a1 = ex2h2(cvtf16x2(s0[2], s0[3]));
            const uint32_t a2 = ex2h2(cvtf16x2(s1[0], s1[1]));
            const uint32_t a3 = ex2h2(cvtf16x2(s1[2], s1[3]));

            const uint32_t vstep = Vb + (uint32_t)(ks * 2048);
#pragma unroll
            for (int g = 0; g < 4; g++) {
                uint32_t r0, r1, r2, r3;
                ldsm4t(r0, r1, r2, r3, vstep + vmoff[g]);
                mma16816(dac[2 * g],     a0, a1, a2, a3, r0, r1);
                mma16816(dac[2 * g + 1], a0, a1, a2, a3, r2, r3);
            }
            mma16816(dl, a0, a1, a2, a3, ONES, ONES);
        }
        __syncthreads();
    }

    // ---- partial l ----
    if (tg == 0) {
        const size_t lb = ((size_t)(b * KS + s)) * Nn + row0 + w * 16 + gid;
        g_pl[lb]     = dl[0];
        g_pl[lb + 8] = dl[2];
    }

    // ---- transpose unnormalized O through smem (stride 132) ----
    float* sD = (float*)smem;
#pragma unroll
    for (int nt = 0; nt < 8; nt++) {
        const int c = nt * 8 + tg * 2;
        const int r = w * 16 + gid;
        sD[c * 132 + r]           = dac[nt][0];
        sD[(c + 1) * 132 + r]     = dac[nt][1];
        sD[c * 132 + r + 8]       = dac[nt][2];
        sD[(c + 1) * 132 + r + 8] = dac[nt][3];
    }
    __syncthreads();

#pragma unroll
    for (int k = 0; k < 8; k++) {
        const int flat = tid + 256 * k;
        const int c = flat >> 5, seg = flat & 31;
        const float4 v = *(const float4*)&sD[c * 132 + seg * 4];
        *(float4*)&g_po[(((size_t)(b * KS + s) * Cc + c)) * Nn + row0 + seg * 4] = v;
    }

    // ---- split-K fixup: last CTA per (b,rowblk) merges ----
    __threadfence();
    if (tid == 0)
        s_last = atomicAdd(&g_ctr[b * (Nn / NQ) + blockIdx.x], 1);
    __syncthreads();

    if (s_last == KS - 1) {
        __threadfence();  // acquire: other split's po/pl visible
        const float gm = __ldg(gamma);
#pragma unroll
        for (int k = 0; k < 8; k++) {
            const int flat = tid + 256 * k;
            const int c = flat >> 5, seg = flat & 31;
            const size_t nidx = (size_t)row0 + seg * 4;
            const float4 o0 = *(const float4*)&g_po[(((size_t)(b * KS) * Cc + c)) * Nn + nidx];
            const float4 o1 = *(const float4*)&g_po[(((size_t)(b * KS + 1) * Cc + c)) * Nn + nidx];
            const float4 l0 = *(const float4*)&g_pl[((size_t)(b * KS)) * Nn + nidx];
            const float4 l1 = *(const float4*)&g_pl[((size_t)(b * KS + 1)) * Nn + nidx];
            const size_t gidx = ((size_t)(b * Cc + c)) * Nn + nidx;
            const float4 xv = *(const float4*)&x[gidx];
            float4 r;
            r.x = fmaf(gm, (o0.x + o1.x) / (l0.x + l1.x), xv.x);
            r.y = fmaf(gm, (o0.y + o1.y) / (l0.y + l1.y), xv.y);
            r.z = fmaf(gm, (o0.z + o1.z) / (l0.z + l1.z), xv.z);
            r.w = fmaf(gm, (o0.w + o1.w) / (l0.w + l1.w), xv.w);
            *(float4*)&out[gidx] = r;
        }
        // reset counter for the next graph replay
        if (tid == 0)
            g_ctr[b * (Nn / NQ) + blockIdx.x] = 0;
    }
}

// ============================================================
extern "C" void kernel_launch(void* const* d_in, const int* in_sizes, int n_in,
                              void* d_out, int out_size)
{
    const float* x     = (const float*)d_in[0];
    const float* Wq    = (const float*)d_in[1];
    const float* bq    = (const float*)d_in[2];
    const float* Wk    = (const float*)d_in[3];
    const float* bk    = (const float*)d_in[4];
    const float* Wv    = (const float*)d_in[5];
    const float* bv    = (const float*)d_in[6];
    const float* gamma = (const float*)d_in[7];
    float* out = (float*)d_out;

    dim3 g1(Nn / 128, Bb);
    qkv_kernel<<<g1, 640>>>(x, Wq, bq, Wk, bk, Wv, bv);

    dim3 g2(Nn / NQ, KS, Bb);
    attn_kernel<<<g2, 256>>>(x, gamma, out);
}

// round 10
// speedup vs baseline: 1.0756x; 1.0756x over previous
#include <cuda_runtime.h>
#include <cuda_fp16.h>
#include <cstdint>

// Problem constants
#define Bb 4
#define Cc 64
#define Dd 8
#define Nn 4096          // H*W
#define LOG2E 1.4426950408889634f
#define TK 128           // keys per tile
#define NQ 128           // queries per CTA
#define KS 4             // key splits
#define NTS (Nn / TK / KS)   // 8 tiles per CTA

// Scratch (allocation-free rule: __device__ globals)
__device__ float  g_q[Bb * Nn * Dd];                 // [b][n][d] f32, scaled by log2e
__device__ __half g_kh[Bb * Nn * Dd];                // [b][n][d] f16
__device__ __half g_vh[Bb * Nn * Cc];                // [b][n][c] f16 key-major
__device__ float  g_po[Bb * KS * Cc * Nn];           // partial O (unnormalized)
__device__ float  g_pl[Bb * KS * Nn];                // partial l

// ---------------- PTX helpers (baseline ISA only) ----------------
__device__ __forceinline__ uint32_t smem_u32(const void* p) {
    uint32_t a;
    asm("{ .reg .u64 t; cvta.to.shared.u64 t, %1; cvt.u32.u64 %0, t; }" : "=r"(a) : "l"(p));
    return a;
}
__device__ __forceinline__ unsigned long long pack2(float a, float b) {
    unsigned long long r;
    asm("mov.b64 %0, {%1, %2};" : "=l"(r) : "f"(a), "f"(b));
    return r;
}
__device__ __forceinline__ void unpack2(unsigned long long v, float& a, float& b) {
    asm("mov.b64 {%0, %1}, %2;" : "=f"(a), "=f"(b) : "l"(v));
}
__device__ __forceinline__ unsigned long long ffma2(unsigned long long a,
                                                    unsigned long long b,
                                                    unsigned long long c) {
    unsigned long long d;
    asm("fma.rn.f32x2 %0, %1, %2, %3;" : "=l"(d) : "l"(a), "l"(b), "l"(c));
    return d;
}
// d = {lo, hi} f16x2 (lo in low half)
__device__ __forceinline__ uint32_t cvtf16x2(float lo, float hi) {
    uint32_t r;
    asm("cvt.rn.f16x2.f32 %0, %1, %2;" : "=r"(r) : "f"(hi), "f"(lo));
    return r;
}
__device__ __forceinline__ uint32_t ex2h2(uint32_t a) {
    uint32_t r;
    asm("ex2.approx.f16x2 %0, %1;" : "=r"(r) : "r"(a));
    return r;
}
__device__ __forceinline__ void lds_v2u64(uint32_t a, unsigned long long& x,
                                          unsigned long long& y) {
    asm volatile("ld.shared.v2.u64 {%0, %1}, [%2];" : "=l"(x), "=l"(y) : "r"(a));
}
__device__ __forceinline__ void ldsm2(uint32_t& r0, uint32_t& r1, uint32_t a) {
    asm volatile("ldmatrix.sync.aligned.m8n8.x2.shared.b16 {%0, %1}, [%2];"
                 : "=r"(r0), "=r"(r1) : "r"(a));
}
__device__ __forceinline__ void ldsm4t(uint32_t& r0, uint32_t& r1, uint32_t& r2,
                                       uint32_t& r3, uint32_t a) {
    asm volatile("ldmatrix.sync.aligned.m8n8.x4.trans.shared.b16 {%0, %1, %2, %3}, [%4];"
                 : "=r"(r0), "=r"(r1), "=r"(r2), "=r"(r3) : "r"(a));
}
__device__ __forceinline__ void cp16(uint32_t dst, const void* src) {
    asm volatile("cp.async.ca.shared.global [%0], [%1], 16;" :: "r"(dst), "l"(src) : "memory");
}
#define CP_COMMIT() asm volatile("cp.async.commit_group;" ::: "memory")
#define CP_WAIT1()  asm volatile("cp.async.wait_group 1;" ::: "memory")
#define CP_WAIT0()  asm volatile("cp.async.wait_group 0;" ::: "memory")

// S[16q x 8k] = Q[16x8] * K^T, f32 accum from zero
__device__ __forceinline__ void mma_qk8(float s[4], uint32_t a0, uint32_t a1,
                                        uint32_t b0) {
    asm volatile(
        "mma.sync.aligned.m16n8k8.row.col.f32.f16.f16.f32 "
        "{%0,%1,%2,%3}, {%4,%5}, {%6}, {%7,%7,%7,%7};"
        : "=f"(s[0]), "=f"(s[1]), "=f"(s[2]), "=f"(s[3])
        : "r"(a0), "r"(a1), "r"(b0), "f"(0.0f));
}
__device__ __forceinline__ void mma16816(float d[4], uint32_t a0, uint32_t a1,
                                         uint32_t a2, uint32_t a3,
                                         uint32_t b0, uint32_t b1) {
    asm volatile(
        "mma.sync.aligned.m16n8k16.row.col.f32.f16.f16.f32 "
        "{%0,%1,%2,%3}, {%4,%5,%6,%7}, {%8,%9}, {%0,%1,%2,%3};"
        : "+f"(d[0]), "+f"(d[1]), "+f"(d[2]), "+f"(d[3])
        : "r"(a0), "r"(a1), "r"(a2), "r"(a3), "r"(b0), "r"(b1));
}

// ============================================================
// Kernel 1: fused 1x1-conv QKV projection — weights in registers,
//   x tile through shared (broadcast LDS). 128-pixel tiles,
//   640 threads = 8 pixel-groups x 80 output channels -> grid 128
//   (single CTA wave on 148 SMs).
//   o in [0,64): V; [64,72): Q (scaled by log2e); [72,80): K.
// grid (Nn/128, Bb)
// ============================================================
__global__ void __launch_bounds__(640) qkv_kernel(
    const float* __restrict__ x,
    const float* __restrict__ Wq, const float* __restrict__ bq,
    const float* __restrict__ Wk, const float* __restrict__ bk,
    const float* __restrict__ Wv, const float* __restrict__ bv)
{
    __shared__ __align__(16) float sx[Cc * 128];   // [c][px] 32 KB
    const uint32_t sb = smem_u32(sx);

    const int tid = threadIdx.x;
    const int pg  = tid / 80;        // 0..7 (16 pixels each)
    const int o   = tid - pg * 80;   // 0..79
    const int b   = blockIdx.y;
    const int n0  = blockIdx.x * 128;

    // ---- stage x tile [64c][128px] via cp.async (2048 x 16B) ----
#pragma unroll
    for (int i = 0; i < 4; i++) {
        const int id = tid + i * 640;
        if (id < 2048) {
            const int c = id >> 5, chunk = id & 31;
            cp16(sb + (uint32_t)(c * 512 + chunk * 16),
                 &x[(size_t)(b * Cc + c) * Nn + n0 + chunk * 4]);
        }
    }
    CP_COMMIT();

    // ---- select weight row + bias ----
    const float* wsrc;
    float bias, scale;
    if (o < 64)      { wsrc = Wv + o * 64;        bias = bv[o];              scale = 1.0f; }
    else if (o < 72) { wsrc = Wq + (o - 64) * 64; bias = bq[o - 64] * LOG2E; scale = LOG2E; }
    else             { wsrc = Wk + (o - 72) * 64; bias = bk[o - 72];         scale = 1.0f; }
    const float4* wp4 = (const float4*)wsrc;

    float4 nw0 = wp4[0], nw1 = wp4[1], nw2 = wp4[2], nw3 = wp4[3];

    unsigned long long acc[8];
#pragma unroll
    for (int i = 0; i < 8; i++) acc[i] = pack2(0.0f, 0.0f);

    CP_WAIT0();
    __syncthreads();

    const uint32_t xrow = sb + (uint32_t)(pg * 64);
#pragma unroll
    for (int cb = 0; cb < 4; cb++) {
        float wf[16];
        wf[0] = nw0.x * scale; wf[1] = nw0.y * scale; wf[2] = nw0.z * scale; wf[3] = nw0.w * scale;
        wf[4] = nw1.x * scale; wf[5] = nw1.y * scale; wf[6] = nw1.z * scale; wf[7] = nw1.w * scale;
        wf[8] = nw2.x * scale; wf[9] = nw2.y * scale; wf[10] = nw2.z * scale; wf[11] = nw2.w * scale;
        wf[12] = nw3.x * scale; wf[13] = nw3.y * scale; wf[14] = nw3.z * scale; wf[15] = nw3.w * scale;
        if (cb < 3) {
            nw0 = wp4[(cb + 1) * 4 + 0];
            nw1 = wp4[(cb + 1) * 4 + 1];
            nw2 = wp4[(cb + 1) * 4 + 2];
            nw3 = wp4[(cb + 1) * 4 + 3];
        }

#pragma unroll
        for (int cc = 0; cc < 16; cc++) {
            const uint32_t xa = xrow + (uint32_t)((cb * 16 + cc) * 512);
            unsigned long long x0, x1, x2, x3, x4, x5, x6, x7;
            lds_v2u64(xa,      x0, x1);
            lds_v2u64(xa + 16, x2, x3);
            lds_v2u64(xa + 32, x4, x5);
            lds_v2u64(xa + 48, x6, x7);
            const unsigned long long wp = pack2(wf[cc], wf[cc]);
            acc[0] = ffma2(wp, x0, acc[0]);
            acc[1] = ffma2(wp, x1, acc[1]);
            acc[2] = ffma2(wp, x2, acc[2]);
            acc[3] = ffma2(wp, x3, acc[3]);
            acc[4] = ffma2(wp, x4, acc[4]);
            acc[5] = ffma2(wp, x5, acc[5]);
            acc[6] = ffma2(wp, x6, acc[6]);
            acc[7] = ffma2(wp, x7, acc[7]);
        }
    }

    // ---- epilogue: add bias, store per class ----
    if (o < 64) {
        __half* vd = &g_vh[((size_t)b * Nn + n0 + pg * 16) * Cc + o];
#pragma unroll
        for (int pp = 0; pp < 8; pp++) {
            float lo, hi;
            unpack2(acc[pp], lo, hi);
            vd[(2 * pp) * Cc]     = __float2half_rn(lo + bias);
            vd[(2 * pp + 1) * Cc] = __float2half_rn(hi + bias);
        }
    } else if (o < 72) {
        const int d = o - 64;
        float* qd = &g_q[((size_t)b * Nn + n0 + pg * 16) * Dd + d];
#pragma unroll
        for (int pp = 0; pp < 8; pp++) {
            float lo, hi;
            unpack2(acc[pp], lo, hi);
            qd[(2 * pp) * Dd]     = lo + bias;
            qd[(2 * pp + 1) * Dd] = hi + bias;
        }
    } else {
        const int d = o - 72;
        __half* kd = &g_kh[((size_t)b * Nn + n0 + pg * 16) * Dd + d];
#pragma unroll
        for (int pp = 0; pp < 8; pp++) {
            float lo, hi;
            unpack2(acc[pp], lo, hi);
            kd[(2 * pp) * Dd]     = __float2half_rn(lo + bias);
            kd[(2 * pp + 1) * Dd] = __float2half_rn(hi + bias);
        }
    }
}

// ============================================================
// Kernel 2: attention, QK^T and P·V on mma.sync; fragments via
//   ldmatrix. grid (32, KS=4, Bb) = 512 CTAs -> ~3.5 CTAs/SM.
//   Writes unnormalized partial O and partial l.
// ============================================================
__global__ void __launch_bounds__(256) attn_kernel()
{
    // 2 bufs x (2KB K + 16KB V); epilogue reuses as 64x132 f32 (33.8KB)
    __shared__ __align__(16) char smem[36864];
    const uint32_t sb = smem_u32(smem);

    const int tid  = threadIdx.x;
    const int w    = tid >> 5;
    const int lane = tid & 31;
    const int gid  = lane >> 2;   // 0..7
    const int tg   = lane & 3;    // 0..3
    const int b    = blockIdx.z;
    const int s    = blockIdx.y;
    const int row0 = blockIdx.x * NQ;
    const int key0 = s * (Nn / KS);

    // ---- Q A-frags for QK mma (constant) ----
    uint32_t qA0, qA1;
    {
        const float* qr = &g_q[((size_t)b * Nn + row0 + w * 16 + gid) * Dd + 2 * tg];
        const float2 qa = *(const float2*)qr;
        const float2 qc = *(const float2*)(qr + 8 * Dd);
        qA0 = cvtf16x2(qa.x, qa.y);
        qA1 = cvtf16x2(qc.x, qc.y);
    }

    // ---- loop-constant ldmatrix lane offsets ----
    const int koffV = ((lane >> 3) & 1) * 8 + (lane & 7);   // key offset within 16
    const int jhalf = lane >> 4;                            // chunk half (0/1)
    uint32_t vmoff[4];
#pragma unroll
    for (int g = 0; g < 4; g++)
        vmoff[g] = (uint32_t)(koffV * 128 + (((g * 2 + jhalf) ^ (koffV & 7)) * 16));
    const uint32_t kmoff = (uint32_t)((lane & 15) * 16);

    float dac[8][4];
#pragma unroll
    for (int nt = 0; nt < 8; nt++)
#pragma unroll
        for (int i = 0; i < 4; i++) dac[nt][i] = 0.f;
    float dl[4] = {0.f, 0.f, 0.f, 0.f};
    const uint32_t ONES = 0x3C003C00u;

    auto prefetch = [&](int t, int buf) {
        const uint32_t kdst = sb + (uint32_t)buf * 18432u;
        const uint32_t vdst = kdst + 2048u;
        if (tid < 128)
            cp16(kdst + (uint32_t)(tid * 16),
                 &g_kh[((size_t)b * Nn + key0 + t * TK + tid) * Dd]);
#pragma unroll
        for (int j = 0; j < 4; j++) {
            const int id = tid + 256 * j;
            const int key = id >> 3, ch = id & 7;
            cp16(vdst + (uint32_t)(key * 128 + ((ch ^ (key & 7)) * 16)),
                 &g_vh[((size_t)(b * Nn + key0 + t * TK + key)) * Cc + ch * 8]);
        }
    };

    prefetch(0, 0);
    CP_COMMIT();

#pragma unroll 1
    for (int t = 0; t < NTS; t++) {
        if (t + 1 < NTS) { prefetch(t + 1, (t + 1) & 1); CP_COMMIT(); CP_WAIT1(); }
        else             { CP_WAIT0(); }
        __syncthreads();

        const uint32_t Kb = sb + (uint32_t)(t & 1) * 18432u;
        const uint32_t Vb = Kb + 2048u;

#pragma unroll
        for (int ks = 0; ks < 8; ks++) {
            uint32_t kb0, kb1;
            ldsm2(kb0, kb1, Kb + (uint32_t)(ks * 256) + kmoff);
            float s0[4], s1[4];
            mma_qk8(s0, qA0, qA1, kb0);
            mma_qk8(s1, qA0, qA1, kb1);

            const uint32_t a0 = ex2h2(cvtf16x2(s0[0], s0[1]));
            const uint32_t a1 = ex2h2(cvtf16x2(s0[2], s0[3]));
            const uint32_t a2 = ex2h2(cvtf16x2(s1[0], s1[1]));
            const uint32_t a3 = ex2h2(cvtf16x2(s1[2], s1[3]));

            const uint32_t vstep = Vb + (uint32_t)(ks * 2048);
#pragma unroll
            for (int g = 0; g < 4; g++) {
                uint32_t r0, r1, r2, r3;
                ldsm4t(r0, r1, r2, r3, vstep + vmoff[g]);
                mma16816(dac[2 * g],     a0, a1, a2, a3, r0, r1);
                mma16816(dac[2 * g + 1], a0, a1, a2, a3, r2, r3);
            }
            mma16816(dl, a0, a1, a2, a3, ONES, ONES);
        }
        __syncthreads();
    }

    // ---- partial l ----
    if (tg == 0) {
        const size_t lb = ((size_t)(b * KS + s)) * Nn + row0 + w * 16 + gid;
        g_pl[lb]     = dl[0];
        g_pl[lb + 8] = dl[2];
    }

    // ---- transpose unnormalized O through smem (stride 132) ----
    float* sD = (float*)smem;
#pragma unroll
    for (int nt = 0; nt < 8; nt++) {
        const int c = nt * 8 + tg * 2;
        const int r = w * 16 + gid;
        sD[c * 132 + r]           = dac[nt][0];
        sD[(c + 1) * 132 + r]     = dac[nt][1];
        sD[c * 132 + r + 8]       = dac[nt][2];
        sD[(c + 1) * 132 + r + 8] = dac[nt][3];
    }
    __syncthreads();

#pragma unroll
    for (int k = 0; k < 8; k++) {
        const int flat = tid + 256 * k;
        const int c = flat >> 5, seg = flat & 31;
        const float4 v = *(const float4*)&sD[c * 132 + seg * 4];
        *(float4*)&g_po[(((size_t)(b * KS + s) * Cc + c)) * Nn + row0 + seg * 4] = v;
    }
}

// ============================================================
// Kernel 3: merge 4 splits + gamma residual (fully parallel)
// ============================================================
__global__ void __launch_bounds__(256) reduce_kernel(
    const float* __restrict__ x,
    const float* __restrict__ gamma,
    float* __restrict__ out)
{
    const int i = blockIdx.x * 256 + threadIdx.x;
    const size_t flat = (size_t)i * 4;
    const int b = (int)(flat / ((size_t)Cc * Nn));
    const int rem = (int)(flat - (size_t)b * Cc * Nn);
    const int c = rem / Nn;
    const int n = rem % Nn;

    float4 os = make_float4(0.f, 0.f, 0.f, 0.f);
    float4 ls = make_float4(0.f, 0.f, 0.f, 0.f);
#pragma unroll
    for (int s = 0; s < KS; s++) {
        const float4 o = *(const float4*)&g_po[(((size_t)(b * KS + s) * Cc + c)) * Nn + n];
        const float4 l = *(const float4*)&g_pl[((size_t)(b * KS + s)) * Nn + n];
        os.x += o.x; os.y += o.y; os.z += o.z; os.w += o.w;
        ls.x += l.x; ls.y += l.y; ls.z += l.z; ls.w += l.w;
    }
    const float4 xv = *(const float4*)&x[flat];
    const float gm = __ldg(gamma);

    float4 r;
    r.x = fmaf(gm, os.x / ls.x, xv.x);
    r.y = fmaf(gm, os.y / ls.y, xv.y);
    r.z = fmaf(gm, os.z / ls.z, xv.z);
    r.w = fmaf(gm, os.w / ls.w, xv.w);
    *(float4*)&out[flat] = r;
}

// ============================================================
extern "C" void kernel_launch(void* const* d_in, const int* in_sizes, int n_in,
                              void* d_out, int out_size)
{
    const float* x     = (const float*)d_in[0];
    const float* Wq    = (const float*)d_in[1];
    const float* bq    = (const float*)d_in[2];
    const float* Wk    = (const float*)d_in[3];
    const float* bk    = (const float*)d_in[4];
    const float* Wv    = (const float*)d_in[5];
    const float* bv    = (const float*)d_in[6];
    const float* gamma = (const float*)d_in[7];
    float* out = (float*)d_out;

    dim3 g1(Nn / 128, Bb);
    qkv_kernel<<<g1, 640>>>(x, Wq, bq, Wk, bk, Wv, bv);

    dim3 g2(Nn / NQ, KS, Bb);
    attn_kernel<<<g2, 256>>>();

    reduce_kernel<<<(Bb * Cc * Nn / 4) / 256, 256>>>(x, gamma, out);
}